// round 5
// baseline (speedup 1.0000x reference)
#include <cuda_runtime.h>
#include <math.h>

#define HSZ 1024
#define WSZ 1024
#define NIMG 12          // B*C = 4*3
#define TILE 32

// ---------------------------------------------------------------------------
// Compile-time Gaussian weights (KSIZE=15, SIGMA=3), evaluated via constexpr
// exp-series so ptxas sees float literals -> FFMA-imm form (rt_SMSP=1).
// __host__ __device__ so device code may reference them without
// --expt-relaxed-constexpr (still constant-folded at compile time).
// ---------------------------------------------------------------------------
__host__ __device__ constexpr double cexp_(double x) {
    double t = 1.0, s = 1.0;
    for (int i = 1; i < 60; ++i) { t *= x / i; s += t; }
    return s;
}
__host__ __device__ constexpr double gsum_() {
    double s = 0.0;
    for (int i = 0; i < 15; ++i) { double d = i - 7; s += cexp_(-d * d / 18.0); }
    return s;
}
__host__ __device__ constexpr float gw_(int k) {
    double d = k - 7; return (float)(cexp_(-d * d / 18.0) / gsum_());
}

// ---------------------------------------------------------------------------
// One fused kernel per 32x32 output tile:
//   load 60x60 halo + pointwise chain -> sA
//   H1: sB[60][46]   V1+LCE: sC[46][46] (x5, zeroed outside image)
//   H2: sD[46][32]   V2+softness+gradient mask -> out
// ---------------------------------------------------------------------------
__global__ __launch_bounds__(256) void proc_kernel(
    const float* __restrict__ x,
    const float* __restrict__ gains,
    const float* __restrict__ p_gamma,
    const float* __restrict__ p_sb,
    const float* __restrict__ p_hr,
    const float* __restrict__ p_br,
    const float* __restrict__ p_ct,
    const float* __restrict__ p_ea,
    const float* __restrict__ p_soft,
    const float* __restrict__ p_int,
    const float* __restrict__ p_rot,
    const float* __restrict__ p_hard,
    float* __restrict__ out)
{
    constexpr float GW[15] = {gw_(0), gw_(1), gw_(2),  gw_(3),  gw_(4),  gw_(5),  gw_(6), gw_(7),
                              gw_(8), gw_(9), gw_(10), gw_(11), gw_(12), gw_(13), gw_(14)};

    __shared__ float sA[60 * 61 + 8];  // pointwise image, 60x60, row stride 61 (+pad: window overrun)
    __shared__ float sB[64 * 47];      // H1 result 60x46, stride 47 (+4 pad rows: strip overrun)
    __shared__ float sC[46 * 47];      // x5 region 46x46, stride 47
    __shared__ float sD[46 * 33];      // H2 result 46x32, stride 33

    const int tid = threadIdx.x;
    const int img = blockIdx.z;        // b*3 + c
    const int ch  = img % 3;
    const int ty0 = blockIdx.y * TILE;
    const int tx0 = blockIdx.x * TILE;

    const float gain = gains[ch];
    const float gam  = p_gamma[0];
    const float sbv  = p_sb[0],  hrv = p_hr[0];
    const float brv  = p_br[0],  ctv = p_ct[0];
    const float eav  = p_ea[0],  sof = p_soft[0];
    const float itn  = p_int[0], hrd = p_hard[0];
    float snt, cst;
    sincosf(p_rot[0] * 0.017453292519943295f, &snt, &cst);

    const float* __restrict__ xin = x + (size_t)img * (HSZ * WSZ);

    // ---- Phase 0: global load + pointwise chain (zero outside image = conv zero-pad) ----
    for (int i = tid; i < 60 * 60; i += 256) {
        int r  = i / 60, cc = i - r * 60;
        int gy = ty0 - 14 + r, gx = tx0 - 14 + cc;
        float v = 0.f;
        if ((unsigned)gy < HSZ && (unsigned)gx < WSZ) {
            v = __ldg(xin + gy * WSZ + gx) * gain;            // white balance
            v = __powf(v, gam);                               // tone curve
            float hi = 1.f / (1.f + __expf((0.5f - v) * 10.f));
            v = v + sbv * (1.f - hi) - hrv * hi;              // shadow/highlight
            v = fminf(fmaxf(v, 0.f), 1.f);
            v = fmaf(ctv, v - 0.5f, 0.5f + brv);              // brightness/contrast
            v = fminf(fmaxf(v, 0.f), 1.f);
        }
        sA[r * 61 + cc] = v;
    }
    __syncthreads();

    // ---- H1: horizontal blur of sA -> sB (60 rows x 46 cols), 1 thread = 12 outputs ----
    {
        int r = tid >> 2, seg = tid & 3;
        if (r < 60) {
            int c0 = seg * 12;                 // segs: 0,12,24,36 (last stores 10)
            float acc[12] = {};
            #pragma unroll
            for (int i = 0; i < 26; ++i) {     // streaming window: 26 loads for 12 outputs
                float v = sA[r * 61 + c0 + i]; // overrun beyond col 59 only feeds unstored accs
                #pragma unroll
                for (int k = 0; k < 15; ++k) {
                    int j = i - k;
                    if (j >= 0 && j < 12) acc[j] = fmaf(v, GW[k], acc[j]);
                }
            }
            #pragma unroll
            for (int j = 0; j < 12; ++j)
                if (c0 + j < 46) sB[r * 47 + c0 + j] = acc[j];
        }
    }
    __syncthreads();

    // ---- V1 + local-contrast epilogue: sC = x5 (zeroed outside image for blur2 pad) ----
    if (tid < 230) {
        int ccol = tid % 46, strip = tid / 46;
        int r0 = strip * 10;                   // strips of 10 rows (last strip: 6 valid)
        int nr = min(10, 46 - r0);
        float acc[10] = {};
        #pragma unroll
        for (int i = 0; i < 24; ++i) {         // rows r0..r0+23 (pad rows only feed unstored accs)
            float v = sB[(r0 + i) * 47 + ccol];
            #pragma unroll
            for (int k = 0; k < 15; ++k) {
                int j = i - k;
                if (j >= 0 && j < 10) acc[j] = fmaf(v, GW[k], acc[j]);
            }
        }
        #pragma unroll
        for (int j = 0; j < 10; ++j) {
            if (j < nr) {
                int rr = r0 + j;
                int gy = ty0 - 7 + rr, gx = tx0 - 7 + ccol;
                float val = 0.f;
                if ((unsigned)gy < HSZ && (unsigned)gx < WSZ) {
                    float a = sA[(rr + 7) * 61 + ccol + 7];   // center (pointwise) value
                    val = fmaf(eav, a - acc[j], a);           // x + ea*(x - local_mean)
                }
                sC[rr * 47 + ccol] = val;
            }
        }
    }
    __syncthreads();

    // ---- H2: horizontal blur of sC -> sD (46 rows x 32 cols), 1 thread = 8 outputs ----
    {
        int r = tid >> 2, seg = tid & 3;
        if (r < 46) {
            int c0 = seg * 8;
            float acc[8] = {};
            #pragma unroll
            for (int i = 0; i < 22; ++i) {
                float v = sC[r * 47 + c0 + i];
                #pragma unroll
                for (int k = 0; k < 15; ++k) {
                    int j = i - k;
                    if (j >= 0 && j < 8) acc[j] = fmaf(v, GW[k], acc[j]);
                }
            }
            #pragma unroll
            for (int j = 0; j < 8; ++j) sD[r * 33 + c0 + j] = acc[j];
        }
    }
    __syncthreads();

    // ---- V2 + softness + gradient ND mask -> out, 1 thread = 4 outputs ----
    {
        int cc = tid & 31, strip = tid >> 5;
        int r0 = strip * 4;
        float acc[4] = {};
        #pragma unroll
        for (int i = 0; i < 18; ++i) {
            float v = sD[(r0 + i) * 33 + cc];
            #pragma unroll
            for (int k = 0; k < 15; ++k) {
                int j = i - k;
                if (j >= 0 && j < 4) acc[j] = fmaf(v, GW[k], acc[j]);
            }
        }
        float* __restrict__ op = out + (size_t)img * (HSZ * WSZ);
        #pragma unroll
        for (int j = 0; j < 4; ++j) {
            int r  = r0 + j;
            int gy = ty0 + r, gx = tx0 + cc;
            float x5c = sC[(r + 7) * 47 + cc + 7];
            float v = sof * acc[j] + (1.f - sof) * x5c;       // softness blend
            float yn = fmaf((float)gy, 2.f / (float)(HSZ - 1), -1.f);
            float xn = fmaf((float)gx, 2.f / (float)(WSZ - 1), -1.f);
            float gr = xn * cst + yn * snt;
            float mask = 1.f / (1.f + __expf(hrd * gr));      // sigmoid(-hardness*gr)
            v = v * (1.f - itn * mask);
            v = fminf(fmaxf(v, 0.f), 1.f);
            op[gy * WSZ + gx] = v;
        }
    }
}

extern "C" void kernel_launch(void* const* d_in, const int* in_sizes, int n_in,
                              void* d_out, int out_size) {
    (void)in_sizes; (void)n_in; (void)out_size;
    dim3 grid(WSZ / TILE, HSZ / TILE, NIMG);   // 32 x 32 x 12 = 12288 CTAs
    proc_kernel<<<grid, 256>>>(
        (const float*)d_in[0],  // x
        (const float*)d_in[1],  // gains
        (const float*)d_in[2],  // gamma
        (const float*)d_in[3],  // shadow_boost
        (const float*)d_in[4],  // highlight_reduce
        (const float*)d_in[5],  // brightness
        (const float*)d_in[6],  // contrast
        (const float*)d_in[7],  // enhance_amount
        (const float*)d_in[8],  // softness
        (const float*)d_in[9],  // intensity
        (const float*)d_in[10], // rotation
        (const float*)d_in[11], // hardness
        (float*)d_out);
}